// round 2
// baseline (speedup 1.0000x reference)
#include <cuda_runtime.h>
#include <math.h>

#define NB 4
#define LQ 5440
#define CC 256
#define HH_ 8
#define LL 4
#define PP 4
#define DD 32
#define LEN_IN 5440
#define M_TOT (NB * LQ)   // 21760

// Scratch (device globals; no runtime allocation)
__device__ float g_value[NB * LEN_IN * CC];   // (n, s, h*d)
__device__ float g_off[NB * LQ * CC];         // (n, q, h*l*p*2)
__device__ float g_attn[NB * LQ * HH_ * LL * PP];
__device__ float g_mid[NB * LQ * CC];         // (n, q, h*d)

// Level geometry (fixed by the problem's setup_inputs)
__device__ __constant__ int c_ww[LL] = {64, 32, 16, 8};
__device__ __constant__ int c_hh[LL] = {64, 32, 16, 8};
__device__ __constant__ int c_s0[LL] = {0, 4096, 5120, 5376};

// ---------------------------------------------------------------------------
// fp32 GEMM + bias: C[M,Ncols] = A[M,K] @ B[K,Ncols] + bias[Ncols]
// 128x64 tile, 256 threads, 8x4 per-thread microtile, K-tile 16.
// Dims used here are exact multiples (M=21760=170*128, Ncols in {128,256}).
// ---------------------------------------------------------------------------
__global__ void __launch_bounds__(256) gemm_bias_kernel(
    const float* __restrict__ A, const float* __restrict__ B,
    const float* __restrict__ bias, float* __restrict__ Cout,
    int M, int Ncols, int K)
{
    __shared__ float As[16][128 + 4];
    __shared__ float Bs[16][64];

    const int t  = threadIdx.x;
    const int tx = t & 15;          // 0..15  -> 4 cols each
    const int ty = t >> 4;          // 0..15  -> 8 rows each
    const int m0 = blockIdx.y * 128;
    const int n0 = blockIdx.x * 64;

    float acc[8][4] = {};

    for (int k0 = 0; k0 < K; k0 += 16) {
        // A tile: 128 rows x 16 k = 2048 floats. Each thread: one row's 8 floats.
        {
            const int am = t >> 1;          // 0..127
            const int ak = (t & 1) * 8;     // 0 or 8
            float4 v0 = *reinterpret_cast<const float4*>(&A[(size_t)(m0 + am) * K + k0 + ak]);
            float4 v1 = *reinterpret_cast<const float4*>(&A[(size_t)(m0 + am) * K + k0 + ak + 4]);
            As[ak + 0][am] = v0.x; As[ak + 1][am] = v0.y;
            As[ak + 2][am] = v0.z; As[ak + 3][am] = v0.w;
            As[ak + 4][am] = v1.x; As[ak + 5][am] = v1.y;
            As[ak + 6][am] = v1.z; As[ak + 7][am] = v1.w;
        }
        // B tile: 16 k x 64 n = 1024 floats. Each thread: one float4 along n.
        {
            const int bk = t >> 4;          // 0..15
            const int bn = (t & 15) * 4;
            float4 v = *reinterpret_cast<const float4*>(&B[(size_t)(k0 + bk) * Ncols + n0 + bn]);
            *reinterpret_cast<float4*>(&Bs[bk][bn]) = v;
        }
        __syncthreads();

        #pragma unroll
        for (int k = 0; k < 16; k++) {
            float a[8], b[4];
            #pragma unroll
            for (int i = 0; i < 8; i++) a[i] = As[k][ty * 8 + i];
            #pragma unroll
            for (int j = 0; j < 4; j++) b[j] = Bs[k][tx * 4 + j];
            #pragma unroll
            for (int i = 0; i < 8; i++)
                #pragma unroll
                for (int j = 0; j < 4; j++)
                    acc[i][j] = fmaf(a[i], b[j], acc[i][j]);
        }
        __syncthreads();
    }

    #pragma unroll
    for (int i = 0; i < 8; i++) {
        const int m = m0 + ty * 8 + i;
        #pragma unroll
        for (int j = 0; j < 4; j++) {
            const int n = n0 + tx * 4 + j;
            Cout[(size_t)m * Ncols + n] = acc[i][j] + bias[n];
        }
    }
}

// ---------------------------------------------------------------------------
// Fused softmax + bilinear sampling.
// One warp per (n, q, h); lane = channel d (D=32).
// ---------------------------------------------------------------------------
__global__ void __launch_bounds__(256) sample_kernel(
    const float* __restrict__ refp,   // (N, LQ, L, 2)
    float* __restrict__ out)          // g_mid (n, q, h*d)
{
    const int warp = (blockIdx.x * blockDim.x + threadIdx.x) >> 5;
    const int lane = threadIdx.x & 31;
    if (warp >= NB * LQ * HH_) return;

    const int h  = warp % HH_;
    const int nq = warp / HH_;        // n*LQ + q
    const int n  = nq / LQ;

    // --- softmax over the 16 (l,p) logits for this head, replicated in both
    // half-warps (reduce over groups of 16 lanes) ---
    const float lg = g_attn[(size_t)nq * (HH_ * LL * PP) + h * (LL * PP) + (lane & 15)];
    float mx = lg;
    #pragma unroll
    for (int s = 8; s >= 1; s >>= 1) mx = fmaxf(mx, __shfl_xor_sync(0xffffffffu, mx, s));
    const float e = __expf(lg - mx);
    float sm = e;
    #pragma unroll
    for (int s = 8; s >= 1; s >>= 1) sm += __shfl_xor_sync(0xffffffffu, sm, s);
    const float attn_v = e / sm;

    // --- per-lane slice of the 32 offset floats (l,p,xy) for this head ---
    const float offv = g_off[(size_t)nq * CC + h * (LL * PP * 2) + lane];

    const float* __restrict__ ref = &refp[(size_t)nq * (LL * 2)];
    const int d = lane;
    float acc = 0.0f;

    #pragma unroll
    for (int lp = 0; lp < LL * PP; lp++) {
        const int l = lp >> 2;
        const float ox = __shfl_sync(0xffffffffu, offv, lp * 2);
        const float oy = __shfl_sync(0xffffffffu, offv, lp * 2 + 1);
        const float a  = __shfl_sync(0xffffffffu, attn_v, lp);

        const float lx = fminf(fmaxf(ref[l * 2 + 0] + ox, 0.0f), 1.0f);
        const float ly = fminf(fmaxf(ref[l * 2 + 1] + oy, 0.0f), 1.0f);

        const int ww = c_ww[l], hh = c_hh[l], s0 = c_s0[l];
        const float x = lx * (float)ww - 0.5f;
        const float y = ly * (float)hh - 0.5f;

        const int x0 = (int)floorf(x);
        const int y0 = (int)floorf(y);
        const int ix0 = min(max(x0, 0), ww - 1);
        const int ix1 = min(max(x0 + 1, 0), ww - 1);
        const int iy0 = min(max(y0, 0), hh - 1);
        const int iy1 = min(max(y0 + 1, 0), hh - 1);

        // weights computed from the CLIPPED integer coords (matches reference)
        const float wxl = (float)ix1 - x;   // pairs with x0 corner
        const float wxr = x - (float)ix0;   // pairs with x1 corner
        const float wyt = (float)iy1 - y;   // pairs with y0 corner
        const float wyb = y - (float)iy0;   // pairs with y1 corner

        const float* __restrict__ base =
            &g_value[((size_t)(n * LEN_IN + s0)) * CC + h * DD + d];
        const float va = base[(size_t)(iy0 * ww + ix0) * CC];
        const float vb = base[(size_t)(iy1 * ww + ix0) * CC];
        const float vc = base[(size_t)(iy0 * ww + ix1) * CC];
        const float vd = base[(size_t)(iy1 * ww + ix1) * CC];

        const float bil = wxl * wyt * va + wxl * wyb * vb
                        + wxr * wyt * vc + wxr * wyb * vd;
        acc = fmaf(a, bil, acc);
    }

    out[(size_t)nq * CC + h * DD + d] = acc;
}

// ---------------------------------------------------------------------------
// Launch
// ---------------------------------------------------------------------------
extern "C" void kernel_launch(void* const* d_in, const int* in_sizes, int n_in,
                              void* d_out, int out_size)
{
    const float* query   = (const float*)d_in[0];
    const float* refp    = (const float*)d_in[1];
    const float* in_flat = (const float*)d_in[2];
    // d_in[3] shapes, d_in[4] starts — fixed, baked into __constant__
    const float* w_off   = (const float*)d_in[5];
    const float* b_off   = (const float*)d_in[6];
    const float* w_attn  = (const float*)d_in[7];
    const float* b_attn  = (const float*)d_in[8];
    const float* w_val   = (const float*)d_in[9];
    const float* b_val   = (const float*)d_in[10];
    const float* w_out   = (const float*)d_in[11];
    const float* b_out   = (const float*)d_in[12];
    float* out = (float*)d_out;

    float *p_value, *p_off, *p_attn, *p_mid;
    cudaGetSymbolAddress((void**)&p_value, g_value);
    cudaGetSymbolAddress((void**)&p_off,   g_off);
    cudaGetSymbolAddress((void**)&p_attn,  g_attn);
    cudaGetSymbolAddress((void**)&p_mid,   g_mid);

    const dim3 blk(256);

    // 1) value projection: (21760 x 256) @ (256 x 256)
    gemm_bias_kernel<<<dim3(CC / 64, M_TOT / 128), blk>>>(
        in_flat, w_val, b_val, p_value, M_TOT, CC, CC);

    // 2) offsets: (21760 x 256) @ (256 x 256)
    gemm_bias_kernel<<<dim3(CC / 64, M_TOT / 128), blk>>>(
        query, w_off, b_off, p_off, M_TOT, CC, CC);

    // 3) attention logits: (21760 x 256) @ (256 x 128)
    gemm_bias_kernel<<<dim3(128 / 64, M_TOT / 128), blk>>>(
        query, w_attn, b_attn, p_attn, M_TOT, 128, CC);

    // 4) fused softmax + bilinear sampling (one warp per (n,q,h))
    {
        const int warps = NB * LQ * HH_;           // 174080
        const int blocks = (warps * 32 + 255) / 256;
        sample_kernel<<<blocks, blk>>>(refp, p_mid);
    }

    // 5) output projection: (21760 x 256) @ (256 x 256) -> d_out
    gemm_bias_kernel<<<dim3(CC / 64, M_TOT / 128), blk>>>(
        p_mid, w_out, b_out, out, M_TOT, CC, CC);
}

// round 3
// speedup vs baseline: 1.1705x; 1.1705x over previous
#include <cuda_runtime.h>
#include <math.h>

#define NB 4
#define LQ 5440
#define CC 256
#define HH_ 8
#define LL 4
#define PP 4
#define DD 32
#define LEN_IN 5440
#define M_TOT (NB * LQ)       // 21760
#define NQP 384               // fused qproj width: 256 offsets + 128 logits

// Scratch (device globals; no runtime allocation)
__device__ float g_value[NB * LEN_IN * CC];    // (n, s, h*d)
__device__ float g_qproj[NB * LQ * NQP];       // (n, q, [off(256) | attn(128)])
__device__ float g_mid[NB * LQ * CC];          // (n, q, h*d)
__device__ float g_wcomb[CC * NQP];            // packed [w_off | w_attn]
__device__ float g_bcomb[NQP];

// Level geometry (fixed by the problem's setup_inputs)
__device__ __constant__ int c_ww[LL] = {64, 32, 16, 8};
__device__ __constant__ int c_hh[LL] = {64, 32, 16, 8};
__device__ __constant__ int c_s0[LL] = {0, 4096, 5120, 5376};

// ---------------------------------------------------------------------------
// Pack [w_off | w_attn] -> g_wcomb, [b_off | b_attn] -> g_bcomb
// ---------------------------------------------------------------------------
__global__ void pack_kernel(const float* __restrict__ w_off,
                            const float* __restrict__ b_off,
                            const float* __restrict__ w_attn,
                            const float* __restrict__ b_attn)
{
    const int idx = blockIdx.x * blockDim.x + threadIdx.x;
    if (idx < CC * NQP) {
        const int k = idx / NQP;
        const int c = idx - k * NQP;
        g_wcomb[idx] = (c < 256) ? w_off[k * 256 + c] : w_attn[k * 128 + (c - 256)];
    }
    if (idx < NQP) {
        g_bcomb[idx] = (idx < 256) ? b_off[idx] : b_attn[idx - 256];
    }
}

// ---------------------------------------------------------------------------
// fp32 GEMM + bias: C[M,Ncols] = A[M,K] @ B[K,Ncols] + bias[Ncols]
// 128x64 tile, 256 threads, 8x4 per-thread microtile, K-tile 16.
// ---------------------------------------------------------------------------
__global__ void __launch_bounds__(256) gemm_bias_kernel(
    const float* __restrict__ A, const float* __restrict__ B,
    const float* __restrict__ bias, float* __restrict__ Cout,
    int M, int Ncols, int K)
{
    __shared__ float As[16][128 + 4];
    __shared__ float Bs[16][64];

    const int t  = threadIdx.x;
    const int tx = t & 15;          // 0..15 -> 4 cols each
    const int ty = t >> 4;          // 0..15 -> 8 rows each
    const int m0 = blockIdx.y * 128;
    const int n0 = blockIdx.x * 64;

    float acc[8][4] = {};

    for (int k0 = 0; k0 < K; k0 += 16) {
        {
            const int am = t >> 1;          // 0..127
            const int ak = (t & 1) * 8;     // 0 or 8
            float4 v0 = *reinterpret_cast<const float4*>(&A[(size_t)(m0 + am) * K + k0 + ak]);
            float4 v1 = *reinterpret_cast<const float4*>(&A[(size_t)(m0 + am) * K + k0 + ak + 4]);
            As[ak + 0][am] = v0.x; As[ak + 1][am] = v0.y;
            As[ak + 2][am] = v0.z; As[ak + 3][am] = v0.w;
            As[ak + 4][am] = v1.x; As[ak + 5][am] = v1.y;
            As[ak + 6][am] = v1.z; As[ak + 7][am] = v1.w;
        }
        {
            const int bk = t >> 4;          // 0..15
            const int bn = (t & 15) * 4;
            float4 v = *reinterpret_cast<const float4*>(&B[(size_t)(k0 + bk) * Ncols + n0 + bn]);
            *reinterpret_cast<float4*>(&Bs[bk][bn]) = v;
        }
        __syncthreads();

        #pragma unroll
        for (int k = 0; k < 16; k++) {
            float a[8], b[4];
            #pragma unroll
            for (int i = 0; i < 8; i++) a[i] = As[k][ty * 8 + i];
            #pragma unroll
            for (int j = 0; j < 4; j++) b[j] = Bs[k][tx * 4 + j];
            #pragma unroll
            for (int i = 0; i < 8; i++)
                #pragma unroll
                for (int j = 0; j < 4; j++)
                    acc[i][j] = fmaf(a[i], b[j], acc[i][j]);
        }
        __syncthreads();
    }

    #pragma unroll
    for (int i = 0; i < 8; i++) {
        const int m = m0 + ty * 8 + i;
        #pragma unroll
        for (int j = 0; j < 4; j++) {
            const int n = n0 + tx * 4 + j;
            Cout[(size_t)m * Ncols + n] = acc[i][j] + bias[n];
        }
    }
}

// ---------------------------------------------------------------------------
// Fused softmax + bilinear sampling. One warp per (n, q, h); lane = channel d.
// Phase 1: lane lp (0..15, duplicated in upper half) computes its tap's
//   fused params: element offset, packed corner steps, 4 attn-premultiplied
//   corner weights. Phase 2: per tap, 6 shuffles + 4 coalesced loads + 4 FMA.
// ---------------------------------------------------------------------------
__global__ void __launch_bounds__(256) sample_kernel(
    const float* __restrict__ refp)   // (N, LQ, L, 2)
{
    const unsigned F = 0xffffffffu;
    const int warp = (blockIdx.x * blockDim.x + threadIdx.x) >> 5;
    const int lane = threadIdx.x & 31;
    if (warp >= NB * LQ * HH_) return;

    const int h  = warp % HH_;
    const int nq = warp / HH_;        // n*LQ + q
    const int n  = nq / LQ;

    const float* __restrict__ qrow = &g_qproj[(size_t)nq * NQP];

    // --- softmax over the 16 (l,p) logits (replicated in both half-warps) ---
    const float lg = qrow[256 + h * (LL * PP) + (lane & 15)];
    float mx = lg;
    #pragma unroll
    for (int s = 8; s >= 1; s >>= 1) mx = fmaxf(mx, __shfl_xor_sync(F, mx, s));
    const float e = __expf(lg - mx);
    float sm = e;
    #pragma unroll
    for (int s = 8; s >= 1; s >>= 1) sm += __shfl_xor_sync(F, sm, s);
    const float attn_v = e / sm;      // valid for tap (lane & 15)

    // --- per-lane slice of the 32 offset floats (l,p,xy) for this head ---
    const float offv = qrow[h * (LL * PP * 2) + lane];

    // --- phase 1: tap params for tap lp = lane & 15 ---
    const int lp = lane & 15;
    const int l  = lp >> 2;
    const float ox = __shfl_sync(F, offv, 2 * lp);
    const float oy = __shfl_sync(F, offv, 2 * lp + 1);

    const float* __restrict__ ref = &refp[(size_t)nq * (LL * 2)];
    const float lx = fminf(fmaxf(ref[l * 2 + 0] + ox, 0.0f), 1.0f);
    const float ly = fminf(fmaxf(ref[l * 2 + 1] + oy, 0.0f), 1.0f);

    const int ww = c_ww[l], hh = c_hh[l], s0 = c_s0[l];
    const float x = lx * (float)ww - 0.5f;
    const float y = ly * (float)hh - 0.5f;

    const int x0 = (int)floorf(x);
    const int y0 = (int)floorf(y);
    const int ix0 = min(max(x0, 0), ww - 1);
    const int ix1 = min(max(x0 + 1, 0), ww - 1);
    const int iy0 = min(max(y0, 0), hh - 1);
    const int iy1 = min(max(y0 + 1, 0), hh - 1);

    // weights from CLIPPED integer coords (matches reference), premul by attn
    const float wxl = (float)ix1 - x;
    const float wxr = x - (float)ix0;
    const float wyt = (float)iy1 - y;
    const float wyb = y - (float)iy0;
    const float wA = attn_v * wxl * wyt;
    const float wB = attn_v * wxl * wyb;
    const float wC = attn_v * wxr * wyt;
    const float wD = attn_v * wxr * wyb;

    // element offset of corner A for this (n, level, pos, head), excluding d
    const int offA  = (n * LEN_IN + s0 + iy0 * ww + ix0) * CC + h * DD;
    const int rstep = (iy1 - iy0) * ww * CC;    // <= 16384, fits 16 bits
    const int cstep = (ix1 - ix0) * CC;         // 0 or 256
    const int steps = rstep | (cstep << 16);

    // --- phase 2: gather-accumulate, lane = channel d ---
    float acc = 0.0f;
    #pragma unroll
    for (int t = 0; t < LL * PP; t++) {
        const int   o  = __shfl_sync(F, offA,  t);
        const int   st = __shfl_sync(F, steps, t);
        const float w0 = __shfl_sync(F, wA, t);
        const float w1 = __shfl_sync(F, wB, t);
        const float w2 = __shfl_sync(F, wC, t);
        const float w3 = __shfl_sync(F, wD, t);
        const int rs = st & 0xFFFF;
        const int cs = st >> 16;
        const float* __restrict__ p = &g_value[o + lane];
        const float va = p[0];
        const float vb = p[rs];
        const float vc = p[cs];
        const float vd = p[rs + cs];
        acc = fmaf(w0, va, acc);
        acc = fmaf(w1, vb, acc);
        acc = fmaf(w2, vc, acc);
        acc = fmaf(w3, vd, acc);
    }

    g_mid[(size_t)nq * CC + h * DD + lane] = acc;
}

// ---------------------------------------------------------------------------
// Launch
// ---------------------------------------------------------------------------
extern "C" void kernel_launch(void* const* d_in, const int* in_sizes, int n_in,
                              void* d_out, int out_size)
{
    const float* query   = (const float*)d_in[0];
    const float* refp    = (const float*)d_in[1];
    const float* in_flat = (const float*)d_in[2];
    // d_in[3] shapes, d_in[4] starts — fixed, baked into __constant__
    const float* w_off   = (const float*)d_in[5];
    const float* b_off   = (const float*)d_in[6];
    const float* w_attn  = (const float*)d_in[7];
    const float* b_attn  = (const float*)d_in[8];
    const float* w_val   = (const float*)d_in[9];
    const float* b_val   = (const float*)d_in[10];
    const float* w_out   = (const float*)d_in[11];
    const float* b_out   = (const float*)d_in[12];
    float* out = (float*)d_out;

    float *p_value, *p_qproj, *p_mid, *p_wcomb, *p_bcomb;
    cudaGetSymbolAddress((void**)&p_value, g_value);
    cudaGetSymbolAddress((void**)&p_qproj, g_qproj);
    cudaGetSymbolAddress((void**)&p_mid,   g_mid);
    cudaGetSymbolAddress((void**)&p_wcomb, g_wcomb);
    cudaGetSymbolAddress((void**)&p_bcomb, g_bcomb);

    const dim3 blk(256);

    // 0) pack fused qproj weights
    pack_kernel<<<(CC * NQP + 255) / 256, blk>>>(w_off, b_off, w_attn, b_attn);

    // 1) value projection: (21760 x 256) @ (256 x 256)
    gemm_bias_kernel<<<dim3(CC / 64, M_TOT / 128), blk>>>(
        in_flat, w_val, b_val, p_value, M_TOT, CC, CC);

    // 2) fused query projection: (21760 x 256) @ (256 x 384)
    gemm_bias_kernel<<<dim3(NQP / 64, M_TOT / 128), blk>>>(
        query, p_wcomb, p_bcomb, p_qproj, M_TOT, NQP, CC);

    // 3) fused softmax + bilinear sampling (one warp per (n,q,h))
    {
        const int warps = NB * LQ * HH_;           // 174080
        const int blocks = (warps * 32 + 255) / 256;
        sample_kernel<<<blocks, blk>>>(refp);
    }

    // 4) output projection: (21760 x 256) @ (256 x 256) -> d_out
    gemm_bias_kernel<<<dim3(CC / 64, M_TOT / 128), blk>>>(
        p_mid, w_out, b_out, out, M_TOT, CC, CC);
}

// round 4
// speedup vs baseline: 1.2302x; 1.0510x over previous
#include <cuda_runtime.h>
#include <math.h>

#define NB 4
#define LQ 5440
#define CC 256
#define HH_ 8
#define LL 4
#define PP 4
#define DD 32
#define LEN_IN 5440
#define M_TOT (NB * LQ)       // 21760
#define NQP 384               // fused qproj width: 256 offsets + 128 logits

// Scratch (device globals; no runtime allocation)
__device__ __align__(128) float g_value[NB * LEN_IN * CC];   // (n, s, h*d)
__device__ __align__(128) float g_qproj[NB * LQ * NQP];      // (n, q, [off|attn])
__device__ __align__(128) float g_mid[NB * LQ * CC];         // (n, q, h*d)
__device__ __align__(128) float g_wcomb[CC * NQP];           // packed [w_off | w_attn]
__device__ __align__(128) float g_bcomb[NQP];

// Level geometry (fixed by the problem's setup_inputs)
__device__ __constant__ int c_ww[LL] = {64, 32, 16, 8};
__device__ __constant__ int c_hh[LL] = {64, 32, 16, 8};
__device__ __constant__ int c_s0[LL] = {0, 4096, 5120, 5376};

// ---------------------------------------------------------------------------
// Pack [w_off | w_attn] -> g_wcomb, [b_off | b_attn] -> g_bcomb
// ---------------------------------------------------------------------------
__global__ void pack_kernel(const float* __restrict__ w_off,
                            const float* __restrict__ b_off,
                            const float* __restrict__ w_attn,
                            const float* __restrict__ b_attn)
{
    const int idx = blockIdx.x * blockDim.x + threadIdx.x;
    if (idx < CC * NQP) {
        const int k = idx / NQP;
        const int c = idx - k * NQP;
        g_wcomb[idx] = (c < 256) ? w_off[k * 256 + c] : w_attn[k * 128 + (c - 256)];
    }
    if (idx < NQP) {
        g_bcomb[idx] = (idx < 256) ? b_off[idx] : b_attn[idx - 256];
    }
}

// ---------------------------------------------------------------------------
// fp32 GEMM + bias: C[M,Ncols] = A[M,K] @ B[K,Ncols] + bias[Ncols]
// 128x128 tile, 256 threads, 8x8 per-thread microtile split as 2x2 of 4x4
// (rows {ty*4, 64+ty*4}, cols {tx*4, 64+tx*4}) for conflict-free LDS.128.
// ---------------------------------------------------------------------------
__global__ void __launch_bounds__(256, 2) gemm_bias_kernel(
    const float* __restrict__ A, const float* __restrict__ B,
    const float* __restrict__ bias, float* __restrict__ Cout,
    int M, int Ncols, int K)
{
    __shared__ float As[16][128 + 4];
    __shared__ float Bs[16][128];

    const int t  = threadIdx.x;
    const int tx = t & 15;          // 0..15
    const int ty = t >> 4;          // 0..15
    const int m0 = blockIdx.y * 128;
    const int n0 = blockIdx.x * 128;

    float acc[8][8] = {};

    for (int k0 = 0; k0 < K; k0 += 16) {
        // A tile: 128 rows x 16 k. Each thread: one row's 8 k-values.
        {
            const int am = t >> 1;          // 0..127
            const int ak = (t & 1) * 8;     // 0 or 8
            const float* Ap = &A[(size_t)(m0 + am) * K + k0 + ak];
            float4 v0 = *reinterpret_cast<const float4*>(Ap);
            float4 v1 = *reinterpret_cast<const float4*>(Ap + 4);
            As[ak + 0][am] = v0.x; As[ak + 1][am] = v0.y;
            As[ak + 2][am] = v0.z; As[ak + 3][am] = v0.w;
            As[ak + 4][am] = v1.x; As[ak + 5][am] = v1.y;
            As[ak + 6][am] = v1.z; As[ak + 7][am] = v1.w;
        }
        // B tile: 16 k x 128 n. Each thread: 8 consecutive n at row k=t>>4.
        {
            const int bk = t >> 4;          // 0..15
            const int bn = (t & 15) * 8;
            const float* Bp = &B[(size_t)(k0 + bk) * Ncols + n0 + bn];
            *reinterpret_cast<float4*>(&Bs[bk][bn])     = *reinterpret_cast<const float4*>(Bp);
            *reinterpret_cast<float4*>(&Bs[bk][bn + 4]) = *reinterpret_cast<const float4*>(Bp + 4);
        }
        __syncthreads();

        #pragma unroll
        for (int k = 0; k < 16; k++) {
            float a[8], b[8];
            *reinterpret_cast<float4*>(&a[0]) = *reinterpret_cast<const float4*>(&As[k][ty * 4]);
            *reinterpret_cast<float4*>(&a[4]) = *reinterpret_cast<const float4*>(&As[k][64 + ty * 4]);
            *reinterpret_cast<float4*>(&b[0]) = *reinterpret_cast<const float4*>(&Bs[k][tx * 4]);
            *reinterpret_cast<float4*>(&b[4]) = *reinterpret_cast<const float4*>(&Bs[k][64 + tx * 4]);
            #pragma unroll
            for (int i = 0; i < 8; i++)
                #pragma unroll
                for (int j = 0; j < 8; j++)
                    acc[i][j] = fmaf(a[i], b[j], acc[i][j]);
        }
        __syncthreads();
    }

    #pragma unroll
    for (int i = 0; i < 8; i++) {
        const int m = m0 + ((i < 4) ? (ty * 4 + i) : (64 + ty * 4 + (i - 4)));
        #pragma unroll
        for (int jh = 0; jh < 2; jh++) {
            const int n = n0 + jh * 64 + tx * 4;
            float4 r;
            r.x = acc[i][jh * 4 + 0] + bias[n + 0];
            r.y = acc[i][jh * 4 + 1] + bias[n + 1];
            r.z = acc[i][jh * 4 + 2] + bias[n + 2];
            r.w = acc[i][jh * 4 + 3] + bias[n + 3];
            *reinterpret_cast<float4*>(&Cout[(size_t)m * Ncols + n]) = r;
        }
    }
}

// ---------------------------------------------------------------------------
// Fused softmax + bilinear sampling. One warp per (n, q, h).
// Phase 1: lane lp (0..15) computes tap lp's fused params (offset, packed
//   corner steps, 4 attn-premultiplied weights).
// Phase 2: lanes regrouped as (tap-group g = lane>>3) x (channel-quad c8 =
//   lane&7). 4 batches x 4 corner LDG.128; each instruction serves 4 taps.
// Phase 3: xor-reduce over tap-groups, lanes 0..7 store one float4 each.
// ---------------------------------------------------------------------------
__global__ void __launch_bounds__(256) sample_kernel(
    const float* __restrict__ refp)   // (N, LQ, L, 2)
{
    const unsigned F = 0xffffffffu;
    const int warp = (blockIdx.x * blockDim.x + threadIdx.x) >> 5;
    const int lane = threadIdx.x & 31;
    if (warp >= NB * LQ * HH_) return;

    const int h  = warp % HH_;
    const int nq = warp / HH_;        // n*LQ + q
    const int n  = nq / LQ;

    const float* __restrict__ qrow = &g_qproj[(size_t)nq * NQP];

    // --- softmax over 16 (l,p) logits (replicated in both half-warps) ---
    const float lg = qrow[256 + h * (LL * PP) + (lane & 15)];
    float mx = lg;
    #pragma unroll
    for (int s = 8; s >= 1; s >>= 1) mx = fmaxf(mx, __shfl_xor_sync(F, mx, s));
    const float e = __expf(lg - mx);
    float sm = e;
    #pragma unroll
    for (int s = 8; s >= 1; s >>= 1) sm += __shfl_xor_sync(F, sm, s);
    const float attn_v = e / sm;      // valid for tap (lane & 15)

    // --- per-lane slice of the 32 offset floats (l,p,xy) for this head ---
    const float offv = qrow[h * (LL * PP * 2) + lane];

    // --- phase 1: tap params for tap lp = lane & 15 ---
    const int lp = lane & 15;
    const int l  = lp >> 2;
    const float ox = __shfl_sync(F, offv, 2 * lp);
    const float oy = __shfl_sync(F, offv, 2 * lp + 1);

    const float* __restrict__ ref = &refp[(size_t)nq * (LL * 2)];
    const float lx = fminf(fmaxf(ref[l * 2 + 0] + ox, 0.0f), 1.0f);
    const float ly = fminf(fmaxf(ref[l * 2 + 1] + oy, 0.0f), 1.0f);

    const int ww = c_ww[l], hh = c_hh[l], s0 = c_s0[l];
    const float x = lx * (float)ww - 0.5f;
    const float y = ly * (float)hh - 0.5f;

    const int x0 = (int)floorf(x);
    const int y0 = (int)floorf(y);
    const int ix0 = min(max(x0, 0), ww - 1);
    const int ix1 = min(max(x0 + 1, 0), ww - 1);
    const int iy0 = min(max(y0, 0), hh - 1);
    const int iy1 = min(max(y0 + 1, 0), hh - 1);

    // weights from CLIPPED integer coords (matches reference), premul by attn
    const float wxl = (float)ix1 - x;
    const float wxr = x - (float)ix0;
    const float wyt = (float)iy1 - y;
    const float wyb = y - (float)iy0;
    const float wA = attn_v * wxl * wyt;
    const float wB = attn_v * wxl * wyb;
    const float wC = attn_v * wxr * wyt;
    const float wD = attn_v * wxr * wyb;

    // element offset of corner A for this (n, level, pos, head), excluding d
    const int offA  = (n * LEN_IN + s0 + iy0 * ww + ix0) * CC + h * DD;
    const int rstep = (iy1 - iy0) * ww * CC;    // <= 16384, fits 16 bits
    const int cstep = (ix1 - ix0) * CC;         // 0 or 256
    const int steps = rstep | (cstep << 16);

    // --- phase 2: vectorized gather. g = tap group, c8 = channel quad ---
    const int g  = lane >> 3;
    const int c8 = lane & 7;
    float4 acc = make_float4(0.f, 0.f, 0.f, 0.f);

    #pragma unroll
    for (int b = 0; b < 4; b++) {
        const int src = b * 4 + g;              // tap index 0..15
        const int   o  = __shfl_sync(F, offA,  src);
        const int   st = __shfl_sync(F, steps, src);
        const float w0 = __shfl_sync(F, wA, src);
        const float w1 = __shfl_sync(F, wB, src);
        const float w2 = __shfl_sync(F, wC, src);
        const float w3 = __shfl_sync(F, wD, src);
        const int rs = st & 0xFFFF;
        const int cs = st >> 16;
        const float* __restrict__ p = &g_value[o + c8 * 4];
        const float4 va = *reinterpret_cast<const float4*>(p);
        const float4 vb = *reinterpret_cast<const float4*>(p + rs);
        const float4 vc = *reinterpret_cast<const float4*>(p + cs);
        const float4 vd = *reinterpret_cast<const float4*>(p + rs + cs);
        acc.x = fmaf(w0, va.x, fmaf(w1, vb.x, fmaf(w2, vc.x, fmaf(w3, vd.x, acc.x))));
        acc.y = fmaf(w0, va.y, fmaf(w1, vb.y, fmaf(w2, vc.y, fmaf(w3, vd.y, acc.y))));
        acc.z = fmaf(w0, va.z, fmaf(w1, vb.z, fmaf(w2, vc.z, fmaf(w3, vd.z, acc.z))));
        acc.w = fmaf(w0, va.w, fmaf(w1, vb.w, fmaf(w2, vc.w, fmaf(w3, vd.w, acc.w))));
    }

    // --- phase 3: reduce over the 4 tap groups (xor 8, then 16) ---
    #pragma unroll
    for (int s = 8; s <= 16; s <<= 1) {
        acc.x += __shfl_xor_sync(F, acc.x, s);
        acc.y += __shfl_xor_sync(F, acc.y, s);
        acc.z += __shfl_xor_sync(F, acc.z, s);
        acc.w += __shfl_xor_sync(F, acc.w, s);
    }

    if (lane < 8) {
        *reinterpret_cast<float4*>(&g_mid[(size_t)nq * CC + h * DD + c8 * 4]) = acc;
    }
}

// ---------------------------------------------------------------------------
// Launch
// ---------------------------------------------------------------------------
extern "C" void kernel_launch(void* const* d_in, const int* in_sizes, int n_in,
                              void* d_out, int out_size)
{
    const float* query   = (const float*)d_in[0];
    const float* refp    = (const float*)d_in[1];
    const float* in_flat = (const float*)d_in[2];
    // d_in[3] shapes, d_in[4] starts — fixed, baked into __constant__
    const float* w_off   = (const float*)d_in[5];
    const float* b_off   = (const float*)d_in[6];
    const float* w_attn  = (const float*)d_in[7];
    const float* b_attn  = (const float*)d_in[8];
    const float* w_val   = (const float*)d_in[9];
    const float* b_val   = (const float*)d_in[10];
    const float* w_out   = (const float*)d_in[11];
    const float* b_out   = (const float*)d_in[12];
    float* out = (float*)d_out;

    float *p_value, *p_qproj, *p_mid, *p_wcomb, *p_bcomb;
    cudaGetSymbolAddress((void**)&p_value, g_value);
    cudaGetSymbolAddress((void**)&p_qproj, g_qproj);
    cudaGetSymbolAddress((void**)&p_mid,   g_mid);
    cudaGetSymbolAddress((void**)&p_wcomb, g_wcomb);
    cudaGetSymbolAddress((void**)&p_bcomb, g_bcomb);

    const dim3 blk(256);

    // 0) pack fused qproj weights
    pack_kernel<<<(CC * NQP + 255) / 256, blk>>>(w_off, b_off, w_attn, b_attn);

    // 1) value projection: (21760 x 256) @ (256 x 256)
    gemm_bias_kernel<<<dim3(CC / 128, M_TOT / 128), blk>>>(
        in_flat, w_val, b_val, p_value, M_TOT, CC, CC);

    // 2) fused query projection: (21760 x 256) @ (256 x 384)
    gemm_bias_kernel<<<dim3(NQP / 128, M_TOT / 128), blk>>>(
        query, p_wcomb, p_bcomb, p_qproj, M_TOT, NQP, CC);

    // 3) fused softmax + bilinear sampling (one warp per (n,q,h))
    {
        const int warps = NB * LQ * HH_;           // 174080
        const int blocks = (warps * 32 + 255) / 256;
        sample_kernel<<<blocks, blk>>>(refp);
    }

    // 4) output projection: (21760 x 256) @ (256 x 256) -> d_out
    gemm_bias_kernel<<<dim3(CC / 128, M_TOT / 128), blk>>>(
        p_mid, w_out, b_out, out, M_TOT, CC, CC);
}